// round 1
// baseline (speedup 1.0000x reference)
#include <cuda_runtime.h>

// ---------------------------------------------------------------------------
// Problem constants
//   h  [B, N, C]            B=4, N=256, C=512
//   e  [B, N, N, C]
//   Wq/Wk/Wv/We [C, H*D]    H=8, D=64, H*D=512
// Outputs (packed into d_out, float32):
//   h_out [B, N, H*D]       = 4*256*512   = 524288 elems
//   e_out [B, N, N, H*D]    = 4*256*256*512 = 134217728 elems
// ---------------------------------------------------------------------------

#define Bb   4
#define Nn   256
#define Cc   512
#define Hh   8
#define Dd   64
#define HD   512           // H*D
#define M_E  (Bb*Nn*Nn)    // 262144 rows of the big GEMM
#define HOUT_ELEMS (Bb*Nn*HD)

// Scratch (no cudaMalloc allowed)
__device__ float g_Q[Bb*Nn*HD];
__device__ float g_K[Bb*Nn*HD];
__device__ float g_V[Bb*Nn*HD];
__device__ float g_s[Bb*Nn*Nn*Hh];   // per-head clipped score sums
__device__ float g_w[Bb*Nn*Nn*Hh];   // softmax weights

// ---------------------------------------------------------------------------
// Tiled SGEMM core: 128x128 block tile, BK=8, 8x8 per thread, 256 threads
// ---------------------------------------------------------------------------
#define BM 128
#define BN 128
#define BK 8
#define TM 8
#define TN 8
#define SPAD 132   // padded leading dim to dodge bank conflicts

__device__ __forceinline__ void sgemm_tile_512(
    const float* __restrict__ A,   // [M, 512] row-major
    const float* __restrict__ Bm,  // [512, 512] row-major
    int row0, int col0,
    float acc[TM][TN],
    float As[BK][SPAD], float Bs[BK][SPAD])
{
    const int tid  = threadIdx.x;
    const int arow = tid >> 1;            // 0..127
    const int acol = (tid & 1) * 4;       // 0 or 4
    const int brow = tid >> 5;            // 0..7
    const int bcol = (tid & 31) * 4;      // 0..124
    const int tx   = tid & 15;
    const int ty   = tid >> 4;

    const float* Aptr = A + (size_t)(row0 + arow) * Cc + acol;
    const float* Bptr = Bm + (size_t)brow * HD + col0 + bcol;

    for (int k0 = 0; k0 < Cc; k0 += BK) {
        float4 av = *reinterpret_cast<const float4*>(Aptr + k0);
        As[acol + 0][arow] = av.x;
        As[acol + 1][arow] = av.y;
        As[acol + 2][arow] = av.z;
        As[acol + 3][arow] = av.w;

        float4 bv = *reinterpret_cast<const float4*>(Bptr + (size_t)k0 * HD);
        *reinterpret_cast<float4*>(&Bs[brow][bcol]) = bv;
        __syncthreads();

        #pragma unroll
        for (int k = 0; k < BK; ++k) {
            float a[TM], b[TN];
            float4 a0 = *reinterpret_cast<const float4*>(&As[k][ty * TM]);
            float4 a1 = *reinterpret_cast<const float4*>(&As[k][ty * TM + 4]);
            a[0]=a0.x; a[1]=a0.y; a[2]=a0.z; a[3]=a0.w;
            a[4]=a1.x; a[5]=a1.y; a[6]=a1.z; a[7]=a1.w;
            float4 b0 = *reinterpret_cast<const float4*>(&Bs[k][tx * TN]);
            float4 b1 = *reinterpret_cast<const float4*>(&Bs[k][tx * TN + 4]);
            b[0]=b0.x; b[1]=b0.y; b[2]=b0.z; b[3]=b0.w;
            b[4]=b1.x; b[5]=b1.y; b[6]=b1.z; b[7]=b1.w;
            #pragma unroll
            for (int i = 0; i < TM; ++i)
                #pragma unroll
                for (int j = 0; j < TN; ++j)
                    acc[i][j] += a[i] * b[j];
        }
        __syncthreads();
    }
}

// ---------------------------------------------------------------------------
// K1: QKV projections.  z = 0/1/2 -> Q/K/V.  M = B*N = 1024.
// ---------------------------------------------------------------------------
__global__ void qkv_kernel(const float* __restrict__ h,
                           const float* __restrict__ Wq,
                           const float* __restrict__ Wk,
                           const float* __restrict__ Wv)
{
    __shared__ float As[BK][SPAD];
    __shared__ float Bs[BK][SPAD];
    const int z = blockIdx.z;
    const float* W = (z == 0) ? Wq : (z == 1) ? Wk : Wv;
    float* O = (z == 0) ? g_Q : (z == 1) ? g_K : g_V;

    const int row0 = blockIdx.y * BM;
    const int col0 = blockIdx.x * BN;
    float acc[TM][TN] = {};
    sgemm_tile_512(h, W, row0, col0, acc, As, Bs);

    const int tx = threadIdx.x & 15;
    const int ty = threadIdx.x >> 4;
    #pragma unroll
    for (int i = 0; i < TM; ++i) {
        size_t m = (size_t)(row0 + ty * TM + i);
        float4* op = reinterpret_cast<float4*>(O + m * HD + col0 + tx * TN);
        op[0] = make_float4(acc[i][0], acc[i][1], acc[i][2], acc[i][3]);
        op[1] = make_float4(acc[i][4], acc[i][5], acc[i][6], acc[i][7]);
    }
}

// ---------------------------------------------------------------------------
// K2: big fused GEMM:  e_out[m, c] = (e[m,:] @ We)[c] * Q[b,i,c]*K[b,j,c]/8
//     m = (b*N + i)*N + j.  BM=128 divides N=256 -> all rows in a block
//     share (b, i); j spans 128 consecutive values.
// ---------------------------------------------------------------------------
__global__ void pe_kernel(const float* __restrict__ e,
                          const float* __restrict__ We,
                          float* __restrict__ eout)
{
    __shared__ float As[BK][SPAD];
    __shared__ float Bs[BK][SPAD];
    const int row0 = blockIdx.y * BM;
    const int col0 = blockIdx.x * BN;
    float acc[TM][TN] = {};
    sgemm_tile_512(e, We, row0, col0, acc, As, Bs);

    const int tx = threadIdx.x & 15;
    const int ty = threadIdx.x >> 4;

    const int bi = row0 >> 8;          // b*N + i (block never crosses i)
    const int j0 = row0 & (Nn - 1);
    const int bidx = bi >> 8;          // b
    const float* qrow  = g_Q + (size_t)bi * HD + col0 + tx * TN;
    const float* kbase = g_K + (size_t)(bidx * Nn) * HD;

    float qv[TN];
    #pragma unroll
    for (int j = 0; j < TN; ++j) qv[j] = qrow[j] * 0.125f;   // 1/sqrt(64)

    #pragma unroll
    for (int i = 0; i < TM; ++i) {
        const int jj = j0 + ty * TM + i;
        const float* krow = kbase + (size_t)jj * HD + col0 + tx * TN;
        float out[TN];
        #pragma unroll
        for (int j = 0; j < TN; ++j) out[j] = acc[i][j] * qv[j] * krow[j];
        size_t m = (size_t)(row0 + ty * TM + i);
        float4* op = reinterpret_cast<float4*>(eout + m * (size_t)HD + col0 + tx * TN);
        op[0] = make_float4(out[0], out[1], out[2], out[3]);
        op[1] = make_float4(out[4], out[5], out[6], out[7]);
    }
}

// ---------------------------------------------------------------------------
// K3: per-head row sums of e_out + clip.  One warp per row (512 floats).
//     lane l covers cols [16l, 16l+16) -> head = l/4; reduce over 4 lanes.
// ---------------------------------------------------------------------------
__global__ void rowsum_kernel(const float* __restrict__ eout)
{
    const int row  = blockIdx.x * 8 + (threadIdx.x >> 5);
    const int lane = threadIdx.x & 31;
    const float* p = eout + (size_t)row * HD + lane * 16;
    float s = 0.f;
    #pragma unroll
    for (int t = 0; t < 4; ++t) {
        float4 v = *reinterpret_cast<const float4*>(p + t * 4);
        s += v.x + v.y + v.z + v.w;
    }
    s += __shfl_down_sync(0xffffffffu, s, 2, 4);
    s += __shfl_down_sync(0xffffffffu, s, 1, 4);
    if ((lane & 3) == 0) {
        s = fminf(fmaxf(s, -5.0f), 5.0f);
        g_s[(size_t)row * Hh + (lane >> 2)] = s;
    }
}

// ---------------------------------------------------------------------------
// K4: softmax over key axis j.  One block per (b, i, h), 256 threads = j.
// ---------------------------------------------------------------------------
__global__ void softmax_kernel()
{
    const int blk = blockIdx.x;        // 0 .. B*N*H-1
    const int hh  = blk & (Hh - 1);
    const int bi  = blk >> 3;
    const int j   = threadIdx.x;

    __shared__ float red[Nn];
    const size_t idx = ((size_t)bi * Nn + j) * Hh + hh;
    const float ev = __expf(g_s[idx]);
    red[j] = ev;
    __syncthreads();
    #pragma unroll
    for (int st = Nn / 2; st > 0; st >>= 1) {
        if (j < st) red[j] += red[j + st];
        __syncthreads();
    }
    g_w[idx] = ev / red[0];
}

// ---------------------------------------------------------------------------
// K5: h_out[b,i,h,d] = sum_j w[b,i,j,h] * V[b,j,h,d].
//     One block per (b,i), 512 threads = c = h*64+d.
// ---------------------------------------------------------------------------
__global__ void attn_out_kernel(float* __restrict__ hout)
{
    const int bi = blockIdx.x;         // b*N + i
    const int c  = threadIdx.x;        // 0..511
    const int hh = c >> 6;

    __shared__ float ws[Nn * Hh];      // 8 KB
    for (int idx = threadIdx.x; idx < Nn * Hh; idx += blockDim.x)
        ws[idx] = g_w[(size_t)bi * Nn * Hh + idx];
    __syncthreads();

    const int b = bi >> 8;
    const float* vb = g_V + (size_t)(b * Nn) * HD + c;
    float acc = 0.f;
    #pragma unroll 8
    for (int j = 0; j < Nn; ++j)
        acc = fmaf(ws[j * Hh + hh], vb[(size_t)j * HD], acc);
    hout[(size_t)bi * HD + c] = acc;
}

// ---------------------------------------------------------------------------
extern "C" void kernel_launch(void* const* d_in, const int* in_sizes, int n_in,
                              void* d_out, int out_size)
{
    const float* h  = (const float*)d_in[0];
    const float* e  = (const float*)d_in[1];
    const float* Wq = (const float*)d_in[2];
    const float* Wk = (const float*)d_in[3];
    const float* Wv = (const float*)d_in[4];
    const float* We = (const float*)d_in[5];

    float* out   = (float*)d_out;
    float* hout  = out;                  // [B,N,H*D]
    float* eout  = out + HOUT_ELEMS;     // [B,N,N,H*D]

    // K1: Q/K/V projections
    {
        dim3 grid(HD / BN, (Bb * Nn) / BM, 3);
        qkv_kernel<<<grid, 256>>>(h, Wq, Wk, Wv);
    }
    // K2: fused pe GEMM + Q*K/sqrt(D) epilogue -> e_out
    {
        dim3 grid(HD / BN, M_E / BM);
        pe_kernel<<<grid, 256>>>(e, We, eout);
    }
    // K3: per-head rowsums + clip
    rowsum_kernel<<<M_E / 8, 256>>>(eout);
    // K4: softmax over j
    softmax_kernel<<<Bb * Nn * Hh, Nn>>>();
    // K5: weighted V -> h_out
    attn_out_kernel<<<Bb * Nn, HD>>>(hout);
}

// round 3
// speedup vs baseline: 1.6339x; 1.6339x over previous
#include <cuda_runtime.h>
#include <cuda_bf16.h>
#include <cstdint>

// ---------------------------------------------------------------------------
//   h  [B, N, C]  B=4, N=256, C=512;  e [B, N, N, C];  W* [C, 512]
// Outputs packed in d_out: h_out [B,N,512] then e_out [B,N,N,512]
// ---------------------------------------------------------------------------
#define Bb   4
#define Nn   256
#define Cc   512
#define Hh   8
#define HD   512
#define M_E  (Bb*Nn*Nn)
#define HOUT_ELEMS (Bb*Nn*HD)

__device__ float g_Q[Bb*Nn*HD];
__device__ float g_K[Bb*Nn*HD];
__device__ float g_V[Bb*Nn*HD];
__device__ float g_s[Bb*Nn*Nn*Hh];
__device__ float g_w[Bb*Nn*Nn*Hh];
__device__ __nv_bfloat16 g_WeT_hi[HD*Cc];   // [n][k]
__device__ __nv_bfloat16 g_WeT_lo[HD*Cc];   // [n][k]

// ===========================================================================
__device__ __forceinline__ uint32_t smem_u32(const void* p) {
    uint32_t a;
    asm("{ .reg .u64 t; cvta.to.shared.u64 t, %1; cvt.u32.u64 %0, t; }" : "=r"(a) : "l"(p));
    return a;
}
__device__ __forceinline__ void cp_async16(uint32_t dst, const void* src) {
    asm volatile("cp.async.cg.shared.global [%0], [%1], 16;" :: "r"(dst), "l"(src));
}
#define CP_COMMIT() asm volatile("cp.async.commit_group;" ::: "memory")
#define CP_WAIT0()  asm volatile("cp.async.wait_group 0;" ::: "memory")

__device__ __forceinline__ void ldsm_x4(uint32_t addr, uint32_t& r0, uint32_t& r1,
                                        uint32_t& r2, uint32_t& r3) {
    asm volatile("ldmatrix.sync.aligned.m8n8.x4.shared.b16 {%0,%1,%2,%3}, [%4];"
        : "=r"(r0), "=r"(r1), "=r"(r2), "=r"(r3) : "r"(addr));
}
__device__ __forceinline__ void mma_bf16(float* d, const uint32_t* a,
                                         uint32_t b0, uint32_t b1) {
    asm volatile("mma.sync.aligned.m16n8k16.row.col.f32.bf16.bf16.f32 "
        "{%0,%1,%2,%3}, {%4,%5,%6,%7}, {%8,%9}, {%0,%1,%2,%3};"
        : "+f"(d[0]), "+f"(d[1]), "+f"(d[2]), "+f"(d[3])
        : "r"(a[0]), "r"(a[1]), "r"(a[2]), "r"(a[3]), "r"(b0), "r"(b1));
}
__device__ __forceinline__ uint32_t pack_split(float a, float b, uint32_t& lo) {
    __nv_bfloat16 ha = __float2bfloat16(a);
    __nv_bfloat16 hb = __float2bfloat16(b);
    __nv_bfloat16 la = __float2bfloat16(a - __bfloat162float(ha));
    __nv_bfloat16 lb = __float2bfloat16(b - __bfloat162float(hb));
    lo = ((uint32_t)__bfloat16_as_ushort(lb) << 16) | __bfloat16_as_ushort(la);
    return ((uint32_t)__bfloat16_as_ushort(hb) << 16) | __bfloat16_as_ushort(ha);
}

// ===========================================================================
// K0: We -> WeT hi/lo bf16 split
// ===========================================================================
__global__ void prep_we_kernel(const float* __restrict__ We) {
    const int n = blockIdx.x;
    const int k = threadIdx.x;
    float x = We[(size_t)k * HD + n];
    __nv_bfloat16 hi = __float2bfloat16(x);
    g_WeT_hi[(size_t)n * Cc + k] = hi;
    g_WeT_lo[(size_t)n * Cc + k] = __float2bfloat16(x - __bfloat162float(hi));
}

// ===========================================================================
// K1: QKV projection (small FFMA SGEMM)
// ===========================================================================
#define BM 128
#define BN 128
#define BK 8
#define TM 8
#define TN 8
#define SPAD 132
__global__ void qkv_kernel(const float* __restrict__ h,
                           const float* __restrict__ Wq,
                           const float* __restrict__ Wk,
                           const float* __restrict__ Wv)
{
    __shared__ float As[BK][SPAD];
    __shared__ float Bs[BK][SPAD];
    const int z = blockIdx.z;
    const float* W = (z == 0) ? Wq : (z == 1) ? Wk : Wv;
    float* O = (z == 0) ? g_Q : (z == 1) ? g_K : g_V;

    const int row0 = blockIdx.y * BM;
    const int col0 = blockIdx.x * BN;
    const int tid  = threadIdx.x;
    const int arow = tid >> 1;
    const int acol = (tid & 1) * 4;
    const int brow = tid >> 5;
    const int bcol = (tid & 31) * 4;
    const int tx   = tid & 15;
    const int ty   = tid >> 4;

    float acc[TM][TN] = {};
    const float* Aptr = h + (size_t)(row0 + arow) * Cc + acol;
    const float* Bptr = W + (size_t)brow * HD + col0 + bcol;

    for (int k0 = 0; k0 < Cc; k0 += BK) {
        float4 av = *reinterpret_cast<const float4*>(Aptr + k0);
        As[acol+0][arow]=av.x; As[acol+1][arow]=av.y; As[acol+2][arow]=av.z; As[acol+3][arow]=av.w;
        float4 bv = *reinterpret_cast<const float4*>(Bptr + (size_t)k0 * HD);
        *reinterpret_cast<float4*>(&Bs[brow][bcol]) = bv;
        __syncthreads();
        #pragma unroll
        for (int k = 0; k < BK; ++k) {
            float a[TM], b[TN];
            float4 a0 = *reinterpret_cast<const float4*>(&As[k][ty*TM]);
            float4 a1 = *reinterpret_cast<const float4*>(&As[k][ty*TM+4]);
            a[0]=a0.x;a[1]=a0.y;a[2]=a0.z;a[3]=a0.w;a[4]=a1.x;a[5]=a1.y;a[6]=a1.z;a[7]=a1.w;
            float4 b0 = *reinterpret_cast<const float4*>(&Bs[k][tx*TN]);
            float4 b1 = *reinterpret_cast<const float4*>(&Bs[k][tx*TN+4]);
            b[0]=b0.x;b[1]=b0.y;b[2]=b0.z;b[3]=b0.w;b[4]=b1.x;b[5]=b1.y;b[6]=b1.z;b[7]=b1.w;
            #pragma unroll
            for (int i = 0; i < TM; ++i)
                #pragma unroll
                for (int j = 0; j < TN; ++j)
                    acc[i][j] += a[i] * b[j];
        }
        __syncthreads();
    }
    #pragma unroll
    for (int i = 0; i < TM; ++i) {
        size_t m = (size_t)(row0 + ty*TM + i);
        float4* op = reinterpret_cast<float4*>(O + m * HD + col0 + tx*TN);
        op[0] = make_float4(acc[i][0], acc[i][1], acc[i][2], acc[i][3]);
        op[1] = make_float4(acc[i][4], acc[i][5], acc[i][6], acc[i][7]);
    }
}

// ===========================================================================
// K2: HMMA bf16-split GEMM (e @ We) + fused Q*K/8 epilogue + rowsums
//     CTA: 128 rows x 128 cols, K=512 in 16 chunks of 32.
//     8 warps: wm = w&3 (row quarter), wn = w>>2 (64-col half = one head).
// ===========================================================================
#define KC 32
#define NCHUNK 16
#define RSTRIDE 80               // 64B data + 16B pad: conflict-free ldmatrix
#define AH_OFF 0
#define AL_OFF 10240
#define BH_OFF 20480
#define BL_OFF 30720
#define BUF_STRIDE 40960
#define SMEM_PE (2*BUF_STRIDE)   // 80 KB

__global__ void __launch_bounds__(256, 1) pe_mma_kernel(
    const float* __restrict__ e, float* __restrict__ eout)
{
    extern __shared__ char smem[];
    const uint32_t sb = smem_u32(smem);
    const int tid  = threadIdx.x;
    const int lane = tid & 31;
    const int w    = tid >> 5;
    const int wm   = w & 3;
    const int wn   = w >> 2;
    const int n0   = blockIdx.x;              // 0..3 col block
    const int m0   = blockIdx.y * 128;

    const int arow  = tid >> 1;               // 0..127
    const int ahalf = tid & 1;                // 16-elem half of the 32-k chunk

    float acc[2][8][4];
    #pragma unroll
    for (int mt = 0; mt < 2; ++mt)
        #pragma unroll
        for (int nt = 0; nt < 8; ++nt)
            #pragma unroll
            for (int i = 0; i < 4; ++i) acc[mt][nt][i] = 0.f;

    const float* eA = e + (size_t)(m0 + arow) * Cc;
    const __nv_bfloat16* bhA = g_WeT_hi + (size_t)(n0*128 + arow) * Cc;
    const __nv_bfloat16* blA = g_WeT_lo + (size_t)(n0*128 + arow) * Cc;
    const uint32_t sts_off = (uint32_t)(arow * RSTRIDE + ahalf * 32);

    float4 a_reg[4];

    // ---- prologue: stage chunk 0 into buf 0 ----
    {
        const int k0 = ahalf * 16;
        cp_async16(sb + BH_OFF + sts_off +  0, bhA + k0);
        cp_async16(sb + BH_OFF + sts_off + 16, bhA + k0 + 8);
        cp_async16(sb + BL_OFF + sts_off +  0, blA + k0);
        cp_async16(sb + BL_OFF + sts_off + 16, blA + k0 + 8);
        CP_COMMIT();
        const float4* ap = reinterpret_cast<const float4*>(eA + k0);
        #pragma unroll
        for (int i = 0; i < 4; ++i) a_reg[i] = ap[i];
        uint4 hv, lv;
        char* ah = smem + AH_OFF + sts_off;
        char* al = smem + AL_OFF + sts_off;
        hv.x = pack_split(a_reg[0].x, a_reg[0].y, lv.x);
        hv.y = pack_split(a_reg[0].z, a_reg[0].w, lv.y);
        hv.z = pack_split(a_reg[1].x, a_reg[1].y, lv.z);
        hv.w = pack_split(a_reg[1].z, a_reg[1].w, lv.w);
        *reinterpret_cast<uint4*>(ah) = hv;
        *reinterpret_cast<uint4*>(al) = lv;
        hv.x = pack_split(a_reg[2].x, a_reg[2].y, lv.x);
        hv.y = pack_split(a_reg[2].z, a_reg[2].w, lv.y);
        hv.z = pack_split(a_reg[3].x, a_reg[3].y, lv.z);
        hv.w = pack_split(a_reg[3].z, a_reg[3].w, lv.w);
        *reinterpret_cast<uint4*>(ah + 16) = hv;
        *reinterpret_cast<uint4*>(al + 16) = lv;
        CP_WAIT0();
        __syncthreads();
    }

    // ---- main loop ----
    for (int s = 0; s < NCHUNK; ++s) {
        const uint32_t buf = (uint32_t)(s & 1) * BUF_STRIDE;
        const uint32_t nb  = (uint32_t)((s + 1) & 1) * BUF_STRIDE;
        const bool more = (s + 1 < NCHUNK);

        if (more) {
            const int k0 = (s + 1) * KC + ahalf * 16;
            cp_async16(sb + nb + BH_OFF + sts_off +  0, bhA + k0);
            cp_async16(sb + nb + BH_OFF + sts_off + 16, bhA + k0 + 8);
            cp_async16(sb + nb + BL_OFF + sts_off +  0, blA + k0);
            cp_async16(sb + nb + BL_OFF + sts_off + 16, blA + k0 + 8);
            CP_COMMIT();
            const float4* ap = reinterpret_cast<const float4*>(eA + k0);
            #pragma unroll
            for (int i = 0; i < 4; ++i) a_reg[i] = ap[i];
        }

        // compute chunk s
        #pragma unroll
        for (int kk = 0; kk < 2; ++kk) {
            const uint32_t kb = (uint32_t)(kk * 32 + (lane >> 4) * 16);
            uint32_t ahi[2][4], alo[2][4];
            #pragma unroll
            for (int mt = 0; mt < 2; ++mt) {
                const uint32_t ra = sb + buf +
                    (uint32_t)((wm*32 + mt*16 + (lane & 15)) * RSTRIDE) + kb;
                ldsm_x4(ra + AH_OFF, ahi[mt][0], ahi[mt][1], ahi[mt][2], ahi[mt][3]);
                ldsm_x4(ra + AL_OFF, alo[mt][0], alo[mt][1], alo[mt][2], alo[mt][3]);
            }
            uint32_t bhi[4][4], blo[4][4];
            #pragma unroll
            for (int g = 0; g < 4; ++g) {
                const uint32_t rb = sb + buf +
                    (uint32_t)((wn*64 + g*16 + (lane & 15)) * RSTRIDE) + kb;
                ldsm_x4(rb + BH_OFF, bhi[g][0], bhi[g][1], bhi[g][2], bhi[g][3]);
                ldsm_x4(rb + BL_OFF, blo[g][0], blo[g][1], blo[g][2], blo[g][3]);
            }
            #pragma unroll
            for (int mt = 0; mt < 2; ++mt)
                #pragma unroll
                for (int nt = 0; nt < 8; ++nt) {
                    const int g = nt >> 1, o = nt & 1;
                    mma_bf16(acc[mt][nt], ahi[mt], bhi[g][o], bhi[g][o+2]);
                    mma_bf16(acc[mt][nt], ahi[mt], blo[g][o], blo[g][o+2]);
                    mma_bf16(acc[mt][nt], alo[mt], bhi[g][o], bhi[g][o+2]);
                }
        }

        if (more) {
            uint4 hv, lv;
            char* ah = smem + nb + AH_OFF + sts_off;
            char* al = smem + nb + AL_OFF + sts_off;
            hv.x = pack_split(a_reg[0].x, a_reg[0].y, lv.x);
            hv.y = pack_split(a_reg[0].z, a_reg[0].w, lv.y);
            hv.z = pack_split(a_reg[1].x, a_reg[1].y, lv.z);
            hv.w = pack_split(a_reg[1].z, a_reg[1].w, lv.w);
            *reinterpret_cast<uint4*>(ah) = hv;
            *reinterpret_cast<uint4*>(al) = lv;
            hv.x = pack_split(a_reg[2].x, a_reg[2].y, lv.x);
            hv.y = pack_split(a_reg[2].z, a_reg[2].w, lv.y);
            hv.z = pack_split(a_reg[3].x, a_reg[3].y, lv.z);
            hv.w = pack_split(a_reg[3].z, a_reg[3].w, lv.w);
            *reinterpret_cast<uint4*>(ah + 16) = hv;
            *reinterpret_cast<uint4*>(al + 16) = lv;
            CP_WAIT0();
        }
        __syncthreads();
    }

    // ---- epilogue: v = acc * (Q*0.125) * K -> e_out; per-head rowsum -> g_s
    const int q  = lane & 3;
    const int rr = lane >> 2;
    const int bi = blockIdx.y >> 1;             // b*N + i
    const int b  = bi >> 8;
    const int jbase = (blockIdx.y & 1) * 128;
    const int cb = n0 * 128 + wn * 64;
    const int head = cb >> 6;

    float2 qv[8];
    #pragma unroll
    for (int nt = 0; nt < 8; ++nt) {
        float2 t = *reinterpret_cast<const float2*>(
            g_Q + (size_t)bi * HD + cb + nt*8 + 2*q);
        qv[nt] = make_float2(t.x * 0.125f, t.y * 0.125f);
    }

    #pragma unroll
    for (int mt = 0; mt < 2; ++mt)
        #pragma unroll
        for (int half = 0; half < 2; ++half) {
            const int r = wm*32 + mt*16 + rr + half*8;
            const size_t m = (size_t)m0 + r;
            const int j = jbase + r;
            const float* kp = g_K + ((size_t)(b * Nn + j)) * HD + cb + 2*q;
            float* op = eout + m * HD + cb + 2*q;
            float hs = 0.f;
            #pragma unroll
            for (int nt = 0; nt < 8; ++nt) {
                float2 kv = *reinterpret_cast<const float2*>(kp + nt*8);
                float v0 = acc[mt][nt][half*2+0] * qv[nt].x * kv.x;
                float v1 = acc[mt][nt][half*2+1] * qv[nt].y * kv.y;
                *reinterpret_cast<float2*>(op + nt*8) = make_float2(v0, v1);
                hs += v0 + v1;
            }
            hs += __shfl_xor_sync(0xffffffffu, hs, 1);
            hs += __shfl_xor_sync(0xffffffffu, hs, 2);
            if (q == 0)
                g_s[m * Hh + head] = fminf(fmaxf(hs, -5.f), 5.f);
        }
}

// ===========================================================================
// K4: softmax over key axis j
// ===========================================================================
__global__ void softmax_kernel()
{
    const int blk = blockIdx.x;
    const int hh  = blk & (Hh - 1);
    const int bi  = blk >> 3;
    const int j   = threadIdx.x;

    __shared__ float red[Nn];
    const size_t idx = ((size_t)bi * Nn + j) * Hh + hh;
    const float ev = __expf(g_s[idx]);
    red[j] = ev;
    __syncthreads();
    #pragma unroll
    for (int st = Nn / 2; st > 0; st >>= 1) {
        if (j < st) red[j] += red[j + st];
        __syncthreads();
    }
    g_w[idx] = ev / red[0];
}

// ===========================================================================
// K5: h_out = softmax weights @ V
// ===========================================================================
__global__ void attn_out_kernel(float* __restrict__ hout)
{
    const int bi = blockIdx.x;
    const int c  = threadIdx.x;
    const int hh = c >> 6;

    __shared__ float ws[Nn * Hh];
    for (int idx = threadIdx.x; idx < Nn * Hh; idx += blockDim.x)
        ws[idx] = g_w[(size_t)bi * Nn * Hh + idx];
    __syncthreads();

    const int b = bi >> 8;
    const float* vb = g_V + (size_t)(b * Nn) * HD + c;
    float acc = 0.f;
    #pragma unroll 8
    for (int j = 0; j < Nn; ++j)
        acc = fmaf(ws[j * Hh + hh], vb[(size_t)j * HD], acc);
    hout[(size_t)bi * HD + c] = acc;
}

// ===========================================================================
extern "C" void kernel_launch(void* const* d_in, const int* in_sizes, int n_in,
                              void* d_out, int out_size)
{
    const float* h  = (const float*)d_in[0];
    const float* e  = (const float*)d_in[1];
    const float* Wq = (const float*)d_in[2];
    const float* Wk = (const float*)d_in[3];
    const float* Wv = (const float*)d_in[4];
    const float* We = (const float*)d_in[5];

    float* out  = (float*)d_out;
    float* hout = out;
    float* eout = out + HOUT_ELEMS;

    cudaFuncSetAttribute(pe_mma_kernel,
                         cudaFuncAttributeMaxDynamicSharedMemorySize, SMEM_PE);

    prep_we_kernel<<<HD, Cc>>>(We);
    {
        dim3 grid(HD / BN, (Bb * Nn) / BM, 3);
        qkv_kernel<<<grid, 256>>>(h, Wq, Wk, Wv);
    }
    {
        dim3 grid(4, M_E / 128);
        pe_mma_kernel<<<grid, 256, SMEM_PE>>>(e, eout);
    }
    softmax_kernel<<<Bb * Nn * Hh, Nn>>>();
    attn_out_kernel<<<Bb * Nn, HD>>>(hout);
}

// round 5
// speedup vs baseline: 4.2076x; 2.5752x over previous
#include <cuda_runtime.h>
#include <cuda_fp16.h>
#include <cstdint>

// ---------------------------------------------------------------------------
//   h  [B, N, C]  B=4, N=256, C=512;  e [B, N, N, C];  W* [C, 512]
// Outputs packed in d_out: h_out [B,N,512] then e_out [B,N,N,512]
// ---------------------------------------------------------------------------
#define Bb   4
#define Nn   256
#define Cc   512
#define Hh   8
#define HD   512
#define ME_ROWS  (Bb*Nn*Nn)
#define HOUT_ELEMS (Bb*Nn*HD)

__device__ float g_Q[Bb*Nn*HD];
__device__ float g_K[Bb*Nn*HD];
__device__ float g_V[Bb*Nn*HD];
__device__ float g_s[Bb*Nn*Nn*Hh];
__device__ float g_w[Bb*Nn*Nn*Hh];
__device__ __half g_WeT_h[HD*Cc];   // [n][k] = fp16(We[k][n])

// ===========================================================================
__device__ __forceinline__ uint32_t smem_u32(const void* p) {
    uint32_t a;
    asm("{ .reg .u64 t; cvta.to.shared.u64 t, %1; cvt.u32.u64 %0, t; }" : "=r"(a) : "l"(p));
    return a;
}
__device__ __forceinline__ void cp_async16(uint32_t dst, const void* src) {
    asm volatile("cp.async.cg.shared.global [%0], [%1], 16;" :: "r"(dst), "l"(src));
}
#define CP_COMMIT() asm volatile("cp.async.commit_group;" ::: "memory")
#define CP_WAIT0()  asm volatile("cp.async.wait_group 0;" ::: "memory")

__device__ __forceinline__ void ldsm_x4(uint32_t addr, uint32_t& r0, uint32_t& r1,
                                        uint32_t& r2, uint32_t& r3) {
    asm volatile("ldmatrix.sync.aligned.m8n8.x4.shared.b16 {%0,%1,%2,%3}, [%4];"
        : "=r"(r0), "=r"(r1), "=r"(r2), "=r"(r3) : "r"(addr));
}
__device__ __forceinline__ void mma_f16(float* d, const uint32_t* a,
                                        uint32_t b0, uint32_t b1) {
    asm volatile("mma.sync.aligned.m16n8k16.row.col.f32.f16.f16.f32 "
        "{%0,%1,%2,%3}, {%4,%5,%6,%7}, {%8,%9}, {%0,%1,%2,%3};"
        : "+f"(d[0]), "+f"(d[1]), "+f"(d[2]), "+f"(d[3])
        : "r"(a[0]), "r"(a[1]), "r"(a[2]), "r"(a[3]), "r"(b0), "r"(b1));
}
__device__ __forceinline__ uint32_t pack_h2(float a, float b) {
    __half2 h = __floats2half2_rn(a, b);
    return *reinterpret_cast<uint32_t*>(&h);
}

// ===========================================================================
// K0: We -> WeT fp16 (transposed)
// ===========================================================================
__global__ void prep_we_kernel(const float* __restrict__ We) {
    const int n = blockIdx.x;
    const int k = threadIdx.x;
    g_WeT_h[(size_t)n * Cc + k] = __float2half_rn(We[(size_t)k * HD + n]);
}

// ===========================================================================
// K1: QKV projection (small FFMA SGEMM, fp32 exact)
// ===========================================================================
#define BM 128
#define BN 128
#define BK 8
#define TM 8
#define TN 8
#define SPAD 132
__global__ void qkv_kernel(const float* __restrict__ h,
                           const float* __restrict__ Wq,
                           const float* __restrict__ Wk,
                           const float* __restrict__ Wv)
{
    __shared__ float As[BK][SPAD];
    __shared__ float Bs[BK][SPAD];
    const int z = blockIdx.z;
    const float* W = (z == 0) ? Wq : (z == 1) ? Wk : Wv;
    float* O = (z == 0) ? g_Q : (z == 1) ? g_K : g_V;

    const int row0 = blockIdx.y * BM;
    const int col0 = blockIdx.x * BN;
    const int tid  = threadIdx.x;
    const int arow = tid >> 1;
    const int acol = (tid & 1) * 4;
    const int brow = tid >> 5;
    const int bcol = (tid & 31) * 4;
    const int tx   = tid & 15;
    const int ty   = tid >> 4;

    float acc[TM][TN] = {};
    const float* Aptr = h + (size_t)(row0 + arow) * Cc + acol;
    const float* Bptr = W + (size_t)brow * HD + col0 + bcol;

    for (int k0 = 0; k0 < Cc; k0 += BK) {
        float4 av = *reinterpret_cast<const float4*>(Aptr + k0);
        As[acol+0][arow]=av.x; As[acol+1][arow]=av.y; As[acol+2][arow]=av.z; As[acol+3][arow]=av.w;
        float4 bv = *reinterpret_cast<const float4*>(Bptr + (size_t)k0 * HD);
        *reinterpret_cast<float4*>(&Bs[brow][bcol]) = bv;
        __syncthreads();
        #pragma unroll
        for (int k = 0; k < BK; ++k) {
            float a[TM], b[TN];
            float4 a0 = *reinterpret_cast<const float4*>(&As[k][ty*TM]);
            float4 a1 = *reinterpret_cast<const float4*>(&As[k][ty*TM+4]);
            a[0]=a0.x;a[1]=a0.y;a[2]=a0.z;a[3]=a0.w;a[4]=a1.x;a[5]=a1.y;a[6]=a1.z;a[7]=a1.w;
            float4 b0 = *reinterpret_cast<const float4*>(&Bs[k][tx*TN]);
            float4 b1 = *reinterpret_cast<const float4*>(&Bs[k][tx*TN+4]);
            b[0]=b0.x;b[1]=b0.y;b[2]=b0.z;b[3]=b0.w;b[4]=b1.x;b[5]=b1.y;b[6]=b1.z;b[7]=b1.w;
            #pragma unroll
            for (int i = 0; i < TM; ++i)
                #pragma unroll
                for (int j = 0; j < TN; ++j)
                    acc[i][j] += a[i] * b[j];
        }
        __syncthreads();
    }
    #pragma unroll
    for (int i = 0; i < TM; ++i) {
        size_t m = (size_t)(row0 + ty*TM + i);
        float4* op = reinterpret_cast<float4*>(O + m * HD + col0 + tx*TN);
        op[0] = make_float4(acc[i][0], acc[i][1], acc[i][2], acc[i][3]);
        op[1] = make_float4(acc[i][4], acc[i][5], acc[i][6], acc[i][7]);
    }
}

// ===========================================================================
// K2: fp16 HMMA GEMM (e @ We) + fused Q*K/8 epilogue + per-head rowsums
//     CTA: 128 rows x 256 cols, K=512 in 16 chunks of 32.  512 threads.
//     16 warps: wm = w&3 (row quarter of 32), wn = w>>2 (64-col group = head).
// ===========================================================================
#define KC 32
#define NCHUNK 16
#define RSTRIDE 80               // 64B data + 16B pad (conflict-free ldmatrix)
#define A_OFF 0                  // 128 x 80 = 10240
#define B_OFF 10240              // 256 x 80 = 20480
#define BUF_STRIDE 30720
#define SMEM_PE (2*BUF_STRIDE)   // 60 KB

__global__ void __launch_bounds__(512, 1) pe_mma_kernel(
    const float* __restrict__ e, float* __restrict__ eout)
{
    extern __shared__ char smem[];
    const uint32_t sb = smem_u32(smem);
    const int tid  = threadIdx.x;
    const int lane = tid & 31;
    const int w    = tid >> 5;        // 0..15
    const int wm   = w & 3;
    const int wn   = w >> 2;
    const int n0   = blockIdx.x;      // 0..1 (256-col half)
    const int m0   = blockIdx.y * 128;

    // A staging: row = tid>>2 (0..127), quarter = tid&3 (8 floats each)
    const int arow = tid >> 2;
    const int aq   = tid & 3;
    const uint32_t a_sts = (uint32_t)(arow * RSTRIDE + aq * 16);
    const float* eA = e + (size_t)(m0 + arow) * Cc + aq * 8;

    // B staging: row = tid>>1 (0..255), half = tid&1 (16 fp16 each)
    const int brow = tid >> 1;
    const int bh   = tid & 1;
    const uint32_t b_sts = (uint32_t)(brow * RSTRIDE + bh * 32);
    const __half* WhA = g_WeT_h + (size_t)(n0 * 256 + brow) * Cc + bh * 16;

    float acc[2][8][4];
    #pragma unroll
    for (int mt = 0; mt < 2; ++mt)
        #pragma unroll
        for (int nt = 0; nt < 8; ++nt)
            #pragma unroll
            for (int i = 0; i < 4; ++i) acc[mt][nt][i] = 0.f;

    float4 a_reg[2];

    // ---- prologue: stage chunk 0 into buf 0 ----
    {
        cp_async16(sb + B_OFF + b_sts +  0, WhA);
        cp_async16(sb + B_OFF + b_sts + 16, WhA + 8);
        CP_COMMIT();
        a_reg[0] = *reinterpret_cast<const float4*>(eA);
        a_reg[1] = *reinterpret_cast<const float4*>(eA + 4);
        uint4 hv;
        hv.x = pack_h2(a_reg[0].x, a_reg[0].y);
        hv.y = pack_h2(a_reg[0].z, a_reg[0].w);
        hv.z = pack_h2(a_reg[1].x, a_reg[1].y);
        hv.w = pack_h2(a_reg[1].z, a_reg[1].w);
        *reinterpret_cast<uint4*>(smem + A_OFF + a_sts) = hv;
        CP_WAIT0();
        __syncthreads();
    }

    // ---- main loop ----
    for (int s = 0; s < NCHUNK; ++s) {
        const uint32_t buf = (uint32_t)(s & 1) * BUF_STRIDE;
        const uint32_t nb  = (uint32_t)((s + 1) & 1) * BUF_STRIDE;
        const bool more = (s + 1 < NCHUNK);

        if (more) {
            const int k0 = (s + 1) * KC;
            cp_async16(sb + nb + B_OFF + b_sts +  0, WhA + k0);
            cp_async16(sb + nb + B_OFF + b_sts + 16, WhA + k0 + 8);
            CP_COMMIT();
            a_reg[0] = *reinterpret_cast<const float4*>(eA + k0);
            a_reg[1] = *reinterpret_cast<const float4*>(eA + k0 + 4);
        }

        // compute chunk s
        #pragma unroll
        for (int kk = 0; kk < 2; ++kk) {
            const uint32_t kb = (uint32_t)(kk * 32 + (lane >> 4) * 16);
            uint32_t af[2][4];
            #pragma unroll
            for (int mt = 0; mt < 2; ++mt) {
                const uint32_t ra = sb + buf + A_OFF +
                    (uint32_t)((wm*32 + mt*16 + (lane & 15)) * RSTRIDE) + kb;
                ldsm_x4(ra, af[mt][0], af[mt][1], af[mt][2], af[mt][3]);
            }
            uint32_t bf[4][4];
            #pragma unroll
            for (int g = 0; g < 4; ++g) {
                const uint32_t rb = sb + buf + B_OFF +
                    (uint32_t)((wn*64 + g*16 + (lane & 15)) * RSTRIDE) + kb;
                ldsm_x4(rb, bf[g][0], bf[g][1], bf[g][2], bf[g][3]);
            }
            #pragma unroll
            for (int mt = 0; mt < 2; ++mt)
                #pragma unroll
                for (int nt = 0; nt < 8; ++nt) {
                    const int g = nt >> 1, o = nt & 1;
                    mma_f16(acc[mt][nt], af[mt], bf[g][o], bf[g][o+2]);
                }
        }

        if (more) {
            uint4 hv;
            hv.x = pack_h2(a_reg[0].x, a_reg[0].y);
            hv.y = pack_h2(a_reg[0].z, a_reg[0].w);
            hv.z = pack_h2(a_reg[1].x, a_reg[1].y);
            hv.w = pack_h2(a_reg[1].z, a_reg[1].w);
            *reinterpret_cast<uint4*>(smem + nb + A_OFF + a_sts) = hv;
            CP_WAIT0();
        }
        __syncthreads();
    }

    // ---- epilogue: v = acc * (Q*0.125) * K -> e_out; per-head rowsum -> g_s
    const int q  = lane & 3;
    const int rr = lane >> 2;
    const int bi = blockIdx.y >> 1;             // b*N + i
    const int b  = bi >> 8;
    const int jbase = (blockIdx.y & 1) * 128;
    const int cb = n0 * 256 + wn * 64;
    const int head = cb >> 6;

    float2 qv[8];
    #pragma unroll
    for (int nt = 0; nt < 8; ++nt) {
        float2 t = *reinterpret_cast<const float2*>(
            g_Q + (size_t)bi * HD + cb + nt*8 + 2*q);
        qv[nt] = make_float2(t.x * 0.125f, t.y * 0.125f);
    }

    #pragma unroll
    for (int mt = 0; mt < 2; ++mt)
        #pragma unroll
        for (int half = 0; half < 2; ++half) {
            const int r = wm*32 + mt*16 + rr + half*8;
            const size_t m = (size_t)m0 + r;
            const int j = jbase + r;
            const float* kp = g_K + ((size_t)(b * Nn + j)) * HD + cb + 2*q;
            float* op = eout + m * HD + cb + 2*q;
            float hs = 0.f;
            #pragma unroll
            for (int nt = 0; nt < 8; ++nt) {
                float2 kv = *reinterpret_cast<const float2*>(kp + nt*8);
                float v0 = acc[mt][nt][half*2+0] * qv[nt].x * kv.x;
                float v1 = acc[mt][nt][half*2+1] * qv[nt].y * kv.y;
                *reinterpret_cast<float2*>(op + nt*8) = make_float2(v0, v1);
                hs += v0 + v1;
            }
            hs += __shfl_xor_sync(0xffffffffu, hs, 1);
            hs += __shfl_xor_sync(0xffffffffu, hs, 2);
            if (q == 0)
                g_s[m * Hh + head] = fminf(fmaxf(hs, -5.f), 5.f);
        }
}

// ===========================================================================
// K4: softmax over key axis j
// ===========================================================================
__global__ void softmax_kernel()
{
    const int blk = blockIdx.x;
    const int hh  = blk & (Hh - 1);
    const int bi  = blk >> 3;
    const int j   = threadIdx.x;

    __shared__ float red[Nn];
    const size_t idx = ((size_t)bi * Nn + j) * Hh + hh;
    const float ev = __expf(g_s[idx]);
    red[j] = ev;
    __syncthreads();
    #pragma unroll
    for (int st = Nn / 2; st > 0; st >>= 1) {
        if (j < st) red[j] += red[j + st];
        __syncthreads();
    }
    g_w[idx] = ev / red[0];
}

// ===========================================================================
// K5: h_out = softmax weights @ V
// ===========================================================================
__global__ void attn_out_kernel(float* __restrict__ hout)
{
    const int bi = blockIdx.x;
    const int c  = threadIdx.x;
    const int hh = c >> 6;

    __shared__ float ws[Nn * Hh];
    for (int idx = threadIdx.x; idx < Nn * Hh; idx += blockDim.x)
        ws[idx] = g_w[(size_t)bi * Nn * Hh + idx];
    __syncthreads();

    const int b = bi >> 8;
    const float* vb = g_V + (size_t)(b * Nn) * HD + c;
    float acc = 0.f;
    #pragma unroll 8
    for (int j = 0; j < Nn; ++j)
        acc = fmaf(ws[j * Hh + hh], vb[(size_t)j * HD], acc);
    hout[(size_t)bi * HD + c] = acc;
}

// ===========================================================================
extern "C" void kernel_launch(void* const* d_in, const int* in_sizes, int n_in,
                              void* d_out, int out_size)
{
    const float* h  = (const float*)d_in[0];
    const float* e  = (const float*)d_in[1];
    const float* Wq = (const float*)d_in[2];
    const float* Wk = (const float*)d_in[3];
    const float* Wv = (const float*)d_in[4];
    const float* We = (const float*)d_in[5];

    float* out  = (float*)d_out;
    float* hout = out;
    float* eout = out + HOUT_ELEMS;

    cudaFuncSetAttribute(pe_mma_kernel,
                         cudaFuncAttributeMaxDynamicSharedMemorySize, SMEM_PE);

    prep_we_kernel<<<HD, Cc>>>(We);
    {
        dim3 grid(HD / BN, (Bb * Nn) / BM, 3);
        qkv_kernel<<<grid, 256>>>(h, Wq, Wk, Wv);
    }
    {
        dim3 grid(2, ME_ROWS / 128);
        pe_mma_kernel<<<grid, 512, SMEM_PE>>>(e, eout);
    }
    softmax_kernel<<<Bb * Nn * Hh, Nn>>>();
    attn_out_kernel<<<Bb * Nn, HD>>>(hout);
}